// round 2
// baseline (speedup 1.0000x reference)
#include <cuda_runtime.h>

#define NN      100000
#define F1      64          // heads*hid for layer 1
#define ET_MAX  1700000     // 1.6M edges + 100k self loops
#define NEG     0.2f
#define EPSV    1e-16f

// ---------------- scratch (static device globals; no cudaMalloc allowed) ----
__device__ float4 g_h1[NN * 16];      // h1[n][64] as 16 float4 per node (25.6MB)
__device__ float4 g_num1[NN * 16];    // layer1 numerator accumulator (25.6MB)
__device__ float4 g_as1[NN];          // per-node a_src, 4 heads
__device__ float4 g_ad1[NN];          // per-node a_dst, 4 heads
__device__ float4 g_m1[NN];           // segment max, 4 heads
__device__ float4 g_den1[NN];         // segment denom, 4 heads
__device__ int    g_src[ET_MAX];
__device__ int    g_dst[ET_MAX];
__device__ float  g_h2[NN];
__device__ float  g_as2[NN];
__device__ float  g_ad2[NN];
__device__ float  g_m2[NN];
__device__ float2 g_nd2[NN];          // (num2, den2) interleaved for red.v2

// ---------------- helpers ---------------------------------------------------
__device__ __forceinline__ float lrelu(float a) { return a > 0.f ? a : NEG * a; }

__device__ __forceinline__ void atomicMaxF(float* a, float v) {
    if (v >= 0.f) atomicMax((int*)a, __float_as_int(v));
    else          atomicMin((unsigned int*)a, __float_as_uint(v));
}

__device__ __forceinline__ void redv4(float* a, float x, float y, float z, float w) {
    asm volatile("red.global.add.v4.f32 [%0], {%1,%2,%3,%4};"
                 :: "l"(a), "f"(x), "f"(y), "f"(z), "f"(w) : "memory");
}
__device__ __forceinline__ void redv2(float* a, float x, float y) {
    asm volatile("red.global.add.v2.f32 [%0], {%1,%2};"
                 :: "l"(a), "f"(x), "f"(y) : "memory");
}

// ---------------- kernels ---------------------------------------------------

// Convert int32 edge list (JAX x64-disabled => int32) and append self-loops.
__global__ void k_edges(const int* __restrict__ ei, int E, int etot) {
    int i = blockIdx.x * blockDim.x + threadIdx.x;
    if (i >= etot) return;
    if (i < E) {
        g_src[i] = ei[i];
        g_dst[i] = ei[E + i];
    } else {
        g_src[i] = i - E;
        g_dst[i] = i - E;
    }
}

// Zero/neg-inf init of all accumulators.
__global__ void k_init() {
    int i = blockIdx.x * blockDim.x + threadIdx.x;     // up to 64*NN
    const float ninf = __int_as_float(0xff800000);
    if (i < NN * 64) ((float*)g_num1)[i] = 0.f;
    if (i < NN * 4) { ((float*)g_m1)[i] = ninf; ((float*)g_den1)[i] = 0.f; }
    if (i < NN)     { g_m2[i] = ninf; g_nd2[i] = make_float2(0.f, 0.f); }
}

// h1 = x @ W1 : [100000,64]x[64,64]. 4 nodes per 256-thread block.
__global__ void k_gemm1(const float* __restrict__ x, const float* __restrict__ W) {
    __shared__ float sW[64 * 64];
    __shared__ float sx[4 * 64];
    int t = threadIdx.x;
#pragma unroll
    for (int i = 0; i < 16; i++) sW[i * 256 + t] = W[i * 256 + t];
    int n0 = blockIdx.x * 4;
    sx[t] = x[n0 * 64 + t];
    __syncthreads();
    int ln = t >> 6, c = t & 63;
    const float* xr = &sx[ln * 64];
    float acc = 0.f;
#pragma unroll
    for (int k = 0; k < 64; k++) acc = fmaf(xr[k], sW[k * 64 + c], acc);
    ((float*)g_h1)[(n0 + ln) * 64 + c] = acc;
}

// Per-node attention projections a_src/a_dst (4 heads). Warp per node.
__global__ void k_attn1(const float* __restrict__ as, const float* __restrict__ ad) {
    __shared__ float ss[64], sd[64];
    int t = threadIdx.x;
    if (t < 64) { ss[t] = as[t]; sd[t] = ad[t]; }
    __syncthreads();
    int lane = t & 31, warp = t >> 5;
    int n = blockIdx.x * 8 + warp;
    const float* hr = ((const float*)g_h1) + n * 64;
    float v1 = hr[lane], v2 = hr[lane + 32];
    float p1s = v1 * ss[lane], p2s = v2 * ss[lane + 32];
    float p1d = v1 * sd[lane], p2d = v2 * sd[lane + 32];
#pragma unroll
    for (int off = 8; off; off >>= 1) {
        p1s += __shfl_down_sync(0xffffffffu, p1s, off, 16);
        p2s += __shfl_down_sync(0xffffffffu, p2s, off, 16);
        p1d += __shfl_down_sync(0xffffffffu, p1d, off, 16);
        p2d += __shfl_down_sync(0xffffffffu, p2d, off, 16);
    }
    float q1s = __shfl_sync(0xffffffffu, p1s, 16);
    float q2s = __shfl_sync(0xffffffffu, p2s, 16);
    float q1d = __shfl_sync(0xffffffffu, p1d, 16);
    float q2d = __shfl_sync(0xffffffffu, p2d, 16);
    if (lane == 0) {
        g_as1[n] = make_float4(p1s, q1s, p2s, q2s);   // heads 0..3
        g_ad1[n] = make_float4(p1d, q1d, p2d, q2d);
    }
}

// Layer1 edge pass A: segment max of leaky_relu(a_src[s]+a_dst[d]) per head.
__global__ void k_edge_A1(int etot) {
    int i = blockIdx.x * blockDim.x + threadIdx.x;
    if (i >= etot) return;
    int s = g_src[i], d = g_dst[i];
    float4 a = g_as1[s], b = g_ad1[d];
    float* m = (float*)&g_m1[d];
    atomicMaxF(m + 0, lrelu(a.x + b.x));
    atomicMaxF(m + 1, lrelu(a.y + b.y));
    atomicMaxF(m + 2, lrelu(a.z + b.z));
    atomicMaxF(m + 3, lrelu(a.w + b.w));
}

// Layer1 edge pass B: e = exp(alpha - m[d]); den[d]+=e; num[d]+=e*h1[s].
__global__ void k_edge_B1(int etot) {
    int i = blockIdx.x * blockDim.x + threadIdx.x;
    if (i >= etot) return;
    int s = g_src[i], d = g_dst[i];
    float4 a = g_as1[s], b = g_ad1[d], m = g_m1[d];
    float e0 = __expf(lrelu(a.x + b.x) - m.x);
    float e1 = __expf(lrelu(a.y + b.y) - m.y);
    float e2 = __expf(lrelu(a.z + b.z) - m.z);
    float e3 = __expf(lrelu(a.w + b.w) - m.w);
    redv4((float*)&g_den1[d], e0, e1, e2, e3);
    const float4* hs = &g_h1[s * 16];
    float* nd = (float*)&g_num1[d * 16];
    float es[4] = {e0, e1, e2, e3};
#pragma unroll
    for (int j = 0; j < 16; j++) {
        float4 v = hs[j];
        float sc = es[j >> 2];
        redv4(nd + 4 * j, v.x * sc, v.y * sc, v.z * sc, v.w * sc);
    }
}

// Layer1 epilogue + layer2 node prep: out1 = elu(num/den + b1);
// h2 = out1 . W2 ; a_src2/a_dst2 = h2 * att2. Warp per node; out1 never stored.
__global__ void k_finish1(const float* __restrict__ b1, const float* __restrict__ W2,
                          const float* __restrict__ as2, const float* __restrict__ ad2) {
    __shared__ float sb[64], sw[64];
    int t = threadIdx.x;
    if (t < 64) { sb[t] = b1[t]; sw[t] = W2[t]; }
    __syncthreads();
    int lane = t & 31, warp = t >> 5;
    int n = blockIdx.x * 8 + warp;
    const float* nr = ((const float*)g_num1) + n * 64;
    float4 dn = g_den1[n];
    float d1v = lane < 16 ? dn.x : dn.y;     // heads 0/1 for cols 0..31
    float d2v = lane < 16 ? dn.z : dn.w;     // heads 2/3 for cols 32..63
    float v1 = nr[lane]      / (d1v + EPSV) + sb[lane];
    float v2 = nr[lane + 32] / (d2v + EPSV) + sb[lane + 32];
    v1 = v1 > 0.f ? v1 : (__expf(v1) - 1.f);
    v2 = v2 > 0.f ? v2 : (__expf(v2) - 1.f);
    float acc = v1 * sw[lane] + v2 * sw[lane + 32];
#pragma unroll
    for (int off = 16; off; off >>= 1) acc += __shfl_down_sync(0xffffffffu, acc, off);
    if (lane == 0) {
        g_h2[n]  = acc;
        g_as2[n] = acc * as2[0];
        g_ad2[n] = acc * ad2[0];
    }
}

// Layer2 edge pass A: scalar segment max.
__global__ void k_edge_A2(int etot) {
    int i = blockIdx.x * blockDim.x + threadIdx.x;
    if (i >= etot) return;
    int s = g_src[i], d = g_dst[i];
    atomicMaxF(&g_m2[d], lrelu(g_as2[s] + g_ad2[d]));
}

// Layer2 edge pass B: fused num/den accumulation (interleaved float2 red).
__global__ void k_edge_B2(int etot) {
    int i = blockIdx.x * blockDim.x + threadIdx.x;
    if (i >= etot) return;
    int s = g_src[i], d = g_dst[i];
    float e = __expf(lrelu(g_as2[s] + g_ad2[d]) - g_m2[d]);
    redv2((float*)&g_nd2[d], e * g_h2[s], e);
}

__global__ void k_final(float* __restrict__ out, const float* __restrict__ b2) {
    int n = blockIdx.x * blockDim.x + threadIdx.x;
    if (n >= NN) return;
    float2 nd = g_nd2[n];
    out[n] = nd.x / (nd.y + EPSV) + b2[0];
}

// ---------------- launch -----------------------------------------------------
extern "C" void kernel_launch(void* const* d_in, const int* in_sizes, int n_in,
                              void* d_out, int out_size) {
    const float* x    = (const float*)d_in[0];
    const int*   ei   = (const int*)d_in[1];          // JAX default => int32
    const float* W1   = (const float*)d_in[2];
    const float* as1  = (const float*)d_in[3];
    const float* ad1  = (const float*)d_in[4];
    const float* b1   = (const float*)d_in[5];
    const float* W2   = (const float*)d_in[6];
    const float* as2  = (const float*)d_in[7];
    const float* ad2  = (const float*)d_in[8];
    const float* b2   = (const float*)d_in[9];
    float*       out  = (float*)d_out;

    int E    = in_sizes[1] / 2;
    int etot = E + NN;

    int eb = (etot + 255) / 256;

    k_edges  <<<eb, 256>>>(ei, E, etot);
    k_init   <<<(NN * 64 + 255) / 256, 256>>>();
    k_gemm1  <<<NN / 4, 256>>>(x, W1);
    k_attn1  <<<NN / 8, 256>>>(as1, ad1);
    k_edge_A1<<<eb, 256>>>(etot);
    k_edge_B1<<<eb, 256>>>(etot);
    k_finish1<<<NN / 8, 256>>>(b1, W2, as2, ad2);
    k_edge_A2<<<eb, 256>>>(etot);
    k_edge_B2<<<eb, 256>>>(etot);
    k_final  <<<(NN + 255) / 256, 256>>>(out, b2);
}

// round 3
// speedup vs baseline: 1.0952x; 1.0952x over previous
#include <cuda_runtime.h>

#define NN      100000
#define ET_MAX  1700000
#define NEG     0.2f
#define EPSV    1e-16f

// ---------------- scratch ----------------------------------------------------
__device__ float  g_h1[NN * 64];      // h1 [N,64] (25.6MB)
__device__ float4 g_as1[NN];          // per-node a_src, 4 heads
__device__ float4 g_ad1[NN];          // per-node a_dst, 4 heads
__device__ int    g_cnt[NN];          // degree histogram
__device__ int    g_rp[NN + 1];       // CSR row pointers (by dst)
__device__ int    g_fill[NN];         // scatter cursors
__device__ int    g_csr[ET_MAX];      // src node per CSR slot
__device__ float  g_h2[NN];
__device__ float  g_as2[NN];
__device__ float  g_ad2[NN];

__device__ __forceinline__ float lrelu(float a) { return a > 0.f ? a : NEG * a; }

// ---------------- CSR build --------------------------------------------------
__global__ void k_zero() {
    int i = blockIdx.x * blockDim.x + threadIdx.x;
    if (i < NN) g_cnt[i] = 0;
}

__global__ void k_hist(const int* __restrict__ ei, int E, int etot) {
    int i = blockIdx.x * blockDim.x + threadIdx.x;
    if (i >= etot) return;
    int d = i < E ? ei[E + i] : i - E;
    atomicAdd(&g_cnt[d], 1);
}

// Single-block exclusive scan of g_cnt -> g_rp / g_fill. 1024 threads.
__global__ void k_scan(int etot) {
    __shared__ int ssum[1024];
    const int PER = (NN + 1023) / 1024;
    int t = threadIdx.x;
    int start = t * PER;
    int end   = start + PER; if (end > NN) end = NN; if (start > NN) start = NN;
    int sum = 0;
    for (int i = start; i < end; i++) sum += g_cnt[i];
    ssum[t] = sum;
    __syncthreads();
    for (int off = 1; off < 1024; off <<= 1) {
        int v = ssum[t];
        int u = (t >= off) ? ssum[t - off] : 0;
        __syncthreads();
        ssum[t] = v + u;
        __syncthreads();
    }
    int run = (t == 0) ? 0 : ssum[t - 1];
    for (int i = start; i < end; i++) {
        g_rp[i] = run; g_fill[i] = run;
        run += g_cnt[i];
    }
    if (t == 1023) g_rp[NN] = etot;
}

__global__ void k_scatter(const int* __restrict__ ei, int E, int etot) {
    int i = blockIdx.x * blockDim.x + threadIdx.x;
    if (i >= etot) return;
    int s, d;
    if (i < E) { s = ei[i]; d = ei[E + i]; }
    else       { s = d = i - E; }
    int pos = atomicAdd(&g_fill[d], 1);
    g_csr[pos] = s;
}

// ---------------- GEMM1 + attention projections fused ------------------------
// h1 = x@W1; a_src1/a_dst1 = per-head dot(h1, att). 4 nodes per 256-thr block.
__global__ void k_gemm1(const float* __restrict__ x, const float* __restrict__ W,
                        const float* __restrict__ as, const float* __restrict__ ad) {
    __shared__ float sW[64 * 64];
    __shared__ float sx[256];
    __shared__ float ss[64], sd[64];
    int t = threadIdx.x;
#pragma unroll
    for (int i = 0; i < 16; i++) sW[i * 256 + t] = W[i * 256 + t];
    if (t < 64) { ss[t] = as[t]; sd[t] = ad[t]; }
    int n0 = blockIdx.x * 4;
    sx[t] = x[n0 * 64 + t];
    __syncthreads();
    int ln = t >> 6, c = t & 63;
    const float* xr = &sx[ln * 64];
    float acc = 0.f;
#pragma unroll
    for (int k = 0; k < 64; k++) acc = fmaf(xr[k], sW[k * 64 + c], acc);
    g_h1[(n0 + ln) * 64 + c] = acc;

    // attention: reduce 16 channels per head. warp = 32 channels = 2 heads.
    float ps = acc * ss[c], pd = acc * sd[c];
#pragma unroll
    for (int off = 8; off; off >>= 1) {
        ps += __shfl_down_sync(0xffffffffu, ps, off, 16);
        pd += __shfl_down_sync(0xffffffffu, pd, off, 16);
    }
    int lane = t & 31, warp = t >> 5;
    int node = n0 + (warp >> 1);
    int half = warp & 1;                       // channels half*32..half*32+31
    float* asn = (float*)&g_as1[node];
    float* adn = (float*)&g_ad1[node];
    if (lane == 0)  { asn[half * 2]     = ps; adn[half * 2]     = pd; }
    if (lane == 16) { asn[half * 2 + 1] = ps; adn[half * 2 + 1] = pd; }
}

// ---------------- layer1 aggregation: warp per dst, no atomics ----------------
// Fuses segment-max, softmax-weighted sum, bias+ELU, W2 dot, layer2 attn proj.
__global__ void k_agg1(const float* __restrict__ b1, const float* __restrict__ W2,
                       const float* __restrict__ as2p, const float* __restrict__ ad2p) {
    int lane = threadIdx.x & 31, warp = threadIdx.x >> 5;
    int d = blockIdx.x * 8 + warp;
    if (d >= NN) return;
    int base = g_rp[d];
    int deg  = g_rp[d + 1] - base;
    float4 ad = g_ad1[d];

    // pass 1: per-head segment max
    const float NINF = -3.4e38f;
    float m0 = NINF, m1 = NINF, m2 = NINF, m3 = NINF;
    for (int i = lane; i < deg; i += 32) {
        int s = g_csr[base + i];
        float4 a = g_as1[s];
        m0 = fmaxf(m0, lrelu(a.x + ad.x));
        m1 = fmaxf(m1, lrelu(a.y + ad.y));
        m2 = fmaxf(m2, lrelu(a.z + ad.z));
        m3 = fmaxf(m3, lrelu(a.w + ad.w));
    }
#pragma unroll
    for (int off = 16; off; off >>= 1) {
        m0 = fmaxf(m0, __shfl_xor_sync(0xffffffffu, m0, off));
        m1 = fmaxf(m1, __shfl_xor_sync(0xffffffffu, m1, off));
        m2 = fmaxf(m2, __shfl_xor_sync(0xffffffffu, m2, off));
        m3 = fmaxf(m3, __shfl_xor_sync(0xffffffffu, m3, off));
    }

    // pass 2: e-weights + accumulate numerator (lane = channel pair) + denom
    int hl = lane >> 4;                         // head select within half
    float accL = 0.f, accH = 0.f;
    float d0 = 0.f, d1 = 0.f, d2 = 0.f, d3 = 0.f;
    for (int chunk = 0; chunk < deg; chunk += 32) {
        int i = chunk + lane;
        int s = 0;
        float e0 = 0.f, e1 = 0.f, e2 = 0.f, e3 = 0.f;
        if (i < deg) {
            s = g_csr[base + i];
            float4 a = g_as1[s];
            e0 = __expf(lrelu(a.x + ad.x) - m0); d0 += e0;
            e1 = __expf(lrelu(a.y + ad.y) - m1); d1 += e1;
            e2 = __expf(lrelu(a.z + ad.z) - m2); d2 += e2;
            e3 = __expf(lrelu(a.w + ad.w) - m3); d3 += e3;
        }
        int cnt = deg - chunk; if (cnt > 32) cnt = 32;
        for (int j = 0; j < cnt; j++) {
            int   sj = __shfl_sync(0xffffffffu, s, j);
            float f0 = __shfl_sync(0xffffffffu, e0, j);
            float f1 = __shfl_sync(0xffffffffu, e1, j);
            float f2 = __shfl_sync(0xffffffffu, e2, j);
            float f3 = __shfl_sync(0xffffffffu, e3, j);
            float elo = hl ? f1 : f0;
            float ehi = hl ? f3 : f2;
            const float* hr = &g_h1[sj * 64];
            accL = fmaf(hr[lane],      elo, accL);
            accH = fmaf(hr[lane + 32], ehi, accH);
        }
    }
#pragma unroll
    for (int off = 16; off; off >>= 1) {
        d0 += __shfl_xor_sync(0xffffffffu, d0, off);
        d1 += __shfl_xor_sync(0xffffffffu, d1, off);
        d2 += __shfl_xor_sync(0xffffffffu, d2, off);
        d3 += __shfl_xor_sync(0xffffffffu, d3, off);
    }

    // epilogue: out1 = elu(num/den + b1); h2 = out1.W2; layer-2 projections
    float denL = (hl ? d1 : d0) + EPSV;
    float denH = (hl ? d3 : d2) + EPSV;
    float v1 = accL / denL + b1[lane];
    float v2 = accH / denH + b1[lane + 32];
    v1 = v1 > 0.f ? v1 : (__expf(v1) - 1.f);
    v2 = v2 > 0.f ? v2 : (__expf(v2) - 1.f);
    float h2 = v1 * W2[lane] + v2 * W2[lane + 32];
#pragma unroll
    for (int off = 16; off; off >>= 1) h2 += __shfl_xor_sync(0xffffffffu, h2, off);
    if (lane == 0) {
        g_h2[d]  = h2;
        g_as2[d] = h2 * as2p[0];
        g_ad2[d] = h2 * ad2p[0];
    }
}

// ---------------- layer2 aggregation + final output ---------------------------
__global__ void k_agg2(float* __restrict__ out, const float* __restrict__ b2) {
    int lane = threadIdx.x & 31, warp = threadIdx.x >> 5;
    int d = blockIdx.x * 8 + warp;
    if (d >= NN) return;
    int base = g_rp[d];
    int deg  = g_rp[d + 1] - base;
    float adv = g_ad2[d];

    float m = -3.4e38f;
    for (int i = lane; i < deg; i += 32) {
        int s = g_csr[base + i];
        m = fmaxf(m, lrelu(g_as2[s] + adv));
    }
#pragma unroll
    for (int off = 16; off; off >>= 1)
        m = fmaxf(m, __shfl_xor_sync(0xffffffffu, m, off));

    float num = 0.f, den = 0.f;
    for (int i = lane; i < deg; i += 32) {
        int s = g_csr[base + i];
        float e = __expf(lrelu(g_as2[s] + adv) - m);
        num = fmaf(e, g_h2[s], num);
        den += e;
    }
#pragma unroll
    for (int off = 16; off; off >>= 1) {
        num += __shfl_xor_sync(0xffffffffu, num, off);
        den += __shfl_xor_sync(0xffffffffu, den, off);
    }
    if (lane == 0) out[d] = num / (den + EPSV) + b2[0];
}

// ---------------- launch -----------------------------------------------------
extern "C" void kernel_launch(void* const* d_in, const int* in_sizes, int n_in,
                              void* d_out, int out_size) {
    const float* x    = (const float*)d_in[0];
    const int*   ei   = (const int*)d_in[1];          // JAX default => int32
    const float* W1   = (const float*)d_in[2];
    const float* as1  = (const float*)d_in[3];
    const float* ad1  = (const float*)d_in[4];
    const float* b1   = (const float*)d_in[5];
    const float* W2   = (const float*)d_in[6];
    const float* as2  = (const float*)d_in[7];
    const float* ad2  = (const float*)d_in[8];
    const float* b2   = (const float*)d_in[9];
    float*       out  = (float*)d_out;

    int E    = in_sizes[1] / 2;
    int etot = E + NN;
    int eb   = (etot + 255) / 256;

    k_zero   <<<(NN + 255) / 256, 256>>>();
    k_hist   <<<eb, 256>>>(ei, E, etot);
    k_scan   <<<1, 1024>>>(etot);
    k_scatter<<<eb, 256>>>(ei, E, etot);
    k_gemm1  <<<NN / 4, 256>>>(x, W1, as1, ad1);
    k_agg1   <<<NN / 8, 256>>>(b1, W2, as2, ad2);
    k_agg2   <<<NN / 8, 256>>>(out, b2);
}

// round 4
// speedup vs baseline: 1.3068x; 1.1933x over previous
#include <cuda_runtime.h>

#define NN      100000
#define ET_MAX  1700000
#define NEG     0.2f
#define EPSV    1e-16f

// ---------------- scratch ----------------------------------------------------
__device__ float  g_h1[NN * 64];      // h1 [N,64] (25.6MB)
__device__ float4 g_as1[NN];          // per-node a_src, 4 heads
__device__ float4 g_ad1[NN];          // per-node a_dst, 4 heads
__device__ int    g_cnt[NN];          // degree histogram
__device__ int    g_rp[NN + 1];       // CSR row pointers (by dst)
__device__ int    g_fill[NN];         // scatter cursors
__device__ int    g_csr[ET_MAX];      // src node per CSR slot
__device__ float2 g_sh2[NN];          // packed {a_src2, h2}
__device__ float  g_ad2[NN];

__device__ __forceinline__ float lrelu(float a) { return a > 0.f ? a : NEG * a; }

// ---------------- CSR build --------------------------------------------------
__global__ void k_zero() {
    int i = blockIdx.x * blockDim.x + threadIdx.x;
    if (i < NN) g_cnt[i] = 0;
}

__global__ void k_hist(const int* __restrict__ ei, int E, int etot) {
    int i = blockIdx.x * blockDim.x + threadIdx.x;
    if (i >= etot) return;
    int d = i < E ? ei[E + i] : i - E;
    atomicAdd(&g_cnt[d], 1);
}

// Single-block exclusive scan of g_cnt -> g_rp / g_fill. 1024 threads.
__global__ void k_scan(int etot) {
    __shared__ int ssum[1024];
    const int PER = (NN + 1023) / 1024;
    int t = threadIdx.x;
    int start = t * PER;
    int end   = start + PER; if (end > NN) end = NN; if (start > NN) start = NN;
    int sum = 0;
    for (int i = start; i < end; i++) sum += g_cnt[i];
    ssum[t] = sum;
    __syncthreads();
    for (int off = 1; off < 1024; off <<= 1) {
        int v = ssum[t];
        int u = (t >= off) ? ssum[t - off] : 0;
        __syncthreads();
        ssum[t] = v + u;
        __syncthreads();
    }
    int run = (t == 0) ? 0 : ssum[t - 1];
    for (int i = start; i < end; i++) {
        g_rp[i] = run; g_fill[i] = run;
        run += g_cnt[i];
    }
    if (t == 1023) g_rp[NN] = etot;
}

__global__ void k_scatter(const int* __restrict__ ei, int E, int etot) {
    int i = blockIdx.x * blockDim.x + threadIdx.x;
    if (i >= etot) return;
    int s, d;
    if (i < E) { s = ei[i]; d = ei[E + i]; }
    else       { s = d = i - E; }
    int pos = atomicAdd(&g_fill[d], 1);
    g_csr[pos] = s;
}

// ---------------- GEMM1 + attention projections fused (persistent) -----------
// h1 = x@W1; a_src1/a_dst1 = per-head dot(h1, att). 4 nodes per tile.
#define GEMM_BLOCKS 1184
__global__ void k_gemm1(const float* __restrict__ x, const float* __restrict__ W,
                        const float* __restrict__ as, const float* __restrict__ ad) {
    __shared__ float sW[64 * 64];
    __shared__ float sx[256];
    __shared__ float ss[64], sd[64];
    int t = threadIdx.x;
#pragma unroll
    for (int i = 0; i < 16; i++) sW[i * 256 + t] = W[i * 256 + t];
    if (t < 64) { ss[t] = as[t]; sd[t] = ad[t]; }
    int ln = t >> 6, c = t & 63;
    int lane = t & 31, warp = t >> 5;
    int half = warp & 1;

    for (int tile = blockIdx.x; tile < NN / 4; tile += GEMM_BLOCKS) {
        int n0 = tile * 4;
        __syncthreads();
        sx[t] = x[n0 * 64 + t];
        __syncthreads();
        const float* xr = &sx[ln * 64];
        float acc = 0.f;
#pragma unroll
        for (int k = 0; k < 64; k++) acc = fmaf(xr[k], sW[k * 64 + c], acc);
        g_h1[(n0 + ln) * 64 + c] = acc;

        float ps = acc * ss[c], pd = acc * sd[c];
#pragma unroll
        for (int off = 8; off; off >>= 1) {
            ps += __shfl_down_sync(0xffffffffu, ps, off, 16);
            pd += __shfl_down_sync(0xffffffffu, pd, off, 16);
        }
        int node = n0 + (warp >> 1);
        float* asn = (float*)&g_as1[node];
        float* adn = (float*)&g_ad1[node];
        if (lane == 0)  { asn[half * 2]     = ps; adn[half * 2]     = pd; }
        if (lane == 16) { asn[half * 2 + 1] = ps; adn[half * 2 + 1] = pd; }
    }
}

// ---------------- layer1 aggregation: warp per dst, no max pass, no atomics ---
__global__ void k_agg1(const float* __restrict__ b1, const float* __restrict__ W2,
                       const float* __restrict__ as2p, const float* __restrict__ ad2p) {
    __shared__ int    ssrc[8][32];
    __shared__ float4 se[8][32];
    int lane = threadIdx.x & 31, w = threadIdx.x >> 5;
    int d = blockIdx.x * 8 + w;
    if (d >= NN) return;
    int base = g_rp[d];
    int deg  = g_rp[d + 1] - base;
    float4 ad = g_ad1[d];

    int hl = lane >> 4;                         // head select within half
    float accL = 0.f, accH = 0.f;
    float d0 = 0.f, d1 = 0.f, d2 = 0.f, d3 = 0.f;

    for (int chunk = 0; chunk < deg; chunk += 32) {
        int i = chunk + lane;
        int s = 0;
        float4 e = make_float4(0.f, 0.f, 0.f, 0.f);
        if (i < deg) {
            s = g_csr[base + i];
            float4 a = g_as1[s];
            e.x = __expf(lrelu(a.x + ad.x)); d0 += e.x;
            e.y = __expf(lrelu(a.y + ad.y)); d1 += e.y;
            e.z = __expf(lrelu(a.z + ad.z)); d2 += e.z;
            e.w = __expf(lrelu(a.w + ad.w)); d3 += e.w;
        }
        __syncwarp();
        ssrc[w][lane] = s;
        se[w][lane]   = e;
        __syncwarp();
        int cnt = deg - chunk; if (cnt > 32) cnt = 32;
        int j = 0;
        for (; j + 4 <= cnt; j += 4) {
            int s0 = ssrc[w][j], s1 = ssrc[w][j + 1], s2 = ssrc[w][j + 2], s3 = ssrc[w][j + 3];
            const float* h0 = &g_h1[s0 * 64];
            const float* h1p = &g_h1[s1 * 64];
            const float* h2p = &g_h1[s2 * 64];
            const float* h3p = &g_h1[s3 * 64];
            float a0 = h0[lane],  b0 = h0[lane + 32];
            float a1 = h1p[lane], b1v = h1p[lane + 32];
            float a2 = h2p[lane], b2v = h2p[lane + 32];
            float a3 = h3p[lane], b3v = h3p[lane + 32];
            float4 E0 = se[w][j], E1 = se[w][j + 1], E2 = se[w][j + 2], E3 = se[w][j + 3];
            accL = fmaf(a0, hl ? E0.y : E0.x, accL);
            accH = fmaf(b0, hl ? E0.w : E0.z, accH);
            accL = fmaf(a1, hl ? E1.y : E1.x, accL);
            accH = fmaf(b1v, hl ? E1.w : E1.z, accH);
            accL = fmaf(a2, hl ? E2.y : E2.x, accL);
            accH = fmaf(b2v, hl ? E2.w : E2.z, accH);
            accL = fmaf(a3, hl ? E3.y : E3.x, accL);
            accH = fmaf(b3v, hl ? E3.w : E3.z, accH);
        }
        for (; j < cnt; j++) {
            int sj = ssrc[w][j];
            float4 E = se[w][j];
            const float* hr = &g_h1[sj * 64];
            accL = fmaf(hr[lane],      hl ? E.y : E.x, accL);
            accH = fmaf(hr[lane + 32], hl ? E.w : E.z, accH);
        }
    }
#pragma unroll
    for (int off = 16; off; off >>= 1) {
        d0 += __shfl_xor_sync(0xffffffffu, d0, off);
        d1 += __shfl_xor_sync(0xffffffffu, d1, off);
        d2 += __shfl_xor_sync(0xffffffffu, d2, off);
        d3 += __shfl_xor_sync(0xffffffffu, d3, off);
    }

    // epilogue: out1 = elu(num/den + b1); h2 = out1.W2; layer-2 projections
    float denL = (hl ? d1 : d0) + EPSV;
    float denH = (hl ? d3 : d2) + EPSV;
    float v1 = accL / denL + b1[lane];
    float v2 = accH / denH + b1[lane + 32];
    v1 = v1 > 0.f ? v1 : (__expf(v1) - 1.f);
    v2 = v2 > 0.f ? v2 : (__expf(v2) - 1.f);
    float h2 = v1 * W2[lane] + v2 * W2[lane + 32];
#pragma unroll
    for (int off = 16; off; off >>= 1) h2 += __shfl_xor_sync(0xffffffffu, h2, off);
    if (lane == 0) {
        g_sh2[d] = make_float2(h2 * as2p[0], h2);
        g_ad2[d] = h2 * ad2p[0];
    }
}

// ---------------- layer2 aggregation + final output (no max pass) -------------
__global__ void k_agg2(float* __restrict__ out, const float* __restrict__ b2) {
    int lane = threadIdx.x & 31, warp = threadIdx.x >> 5;
    int d = blockIdx.x * 8 + warp;
    if (d >= NN) return;
    int base = g_rp[d];
    int deg  = g_rp[d + 1] - base;
    float adv = g_ad2[d];

    float num = 0.f, den = 0.f;
    for (int i = lane; i < deg; i += 32) {
        int s = g_csr[base + i];
        float2 sh = g_sh2[s];                  // {a_src2, h2}
        float e = __expf(lrelu(sh.x + adv));
        num = fmaf(e, sh.y, num);
        den += e;
    }
#pragma unroll
    for (int off = 16; off; off >>= 1) {
        num += __shfl_xor_sync(0xffffffffu, num, off);
        den += __shfl_xor_sync(0xffffffffu, den, off);
    }
    if (lane == 0) out[d] = num / (den + EPSV) + b2[0];
}

// ---------------- launch -----------------------------------------------------
extern "C" void kernel_launch(void* const* d_in, const int* in_sizes, int n_in,
                              void* d_out, int out_size) {
    const float* x    = (const float*)d_in[0];
    const int*   ei   = (const int*)d_in[1];          // JAX default => int32
    const float* W1   = (const float*)d_in[2];
    const float* as1  = (const float*)d_in[3];
    const float* ad1  = (const float*)d_in[4];
    const float* b1   = (const float*)d_in[5];
    const float* W2   = (const float*)d_in[6];
    const float* as2  = (const float*)d_in[7];
    const float* ad2  = (const float*)d_in[8];
    const float* b2   = (const float*)d_in[9];
    float*       out  = (float*)d_out;

    int E    = in_sizes[1] / 2;
    int etot = E + NN;
    int eb   = (etot + 255) / 256;

    k_zero   <<<(NN + 255) / 256, 256>>>();
    k_hist   <<<eb, 256>>>(ei, E, etot);
    k_scan   <<<1, 1024>>>(etot);
    k_scatter<<<eb, 256>>>(ei, E, etot);
    k_gemm1  <<<GEMM_BLOCKS, 256>>>(x, W1, as1, ad1);
    k_agg1   <<<NN / 8, 256>>>(b1, W2, as2, ad2);
    k_agg2   <<<NN / 8, 256>>>(out, b2);
}

// round 5
// speedup vs baseline: 2.2322x; 1.7081x over previous
#include <cuda_runtime.h>

#define NN      100000
#define ET_MAX  1700000
#define NEG     0.2f
#define EPSV    1e-16f
#define NB      98              // ceil(NN/1024)

// ---------------- scratch ----------------------------------------------------
__device__ float  g_h1[NN * 64];      // h1 [N,64] (25.6MB)
__device__ float4 g_as1[NN];          // per-node a_src, 4 heads
__device__ float4 g_ad1[NN];          // per-node a_dst, 4 heads
__device__ int    g_cnt[NN];          // degree histogram (init 1 = self loop)
__device__ int    g_rp[NN + 1];       // CSR row pointers (by dst)
__device__ int    g_fill[NN];         // scatter cursors
__device__ int    g_csr[ET_MAX];      // src node per CSR slot
__device__ int    g_bsum[NB];         // per-block degree sums
__device__ int    g_boff[NB];         // per-block exclusive offsets
__device__ float2 g_sh2[NN];          // packed {a_src2, h2}
__device__ float  g_ad2[NN];

__device__ __forceinline__ float lrelu(float a) { return a > 0.f ? a : NEG * a; }

// ---------------- CSR build (all coalesced) ----------------------------------
__global__ void k_zero() {
    int i = blockIdx.x * blockDim.x + threadIdx.x;
    if (i < NN) g_cnt[i] = 1;          // self-loop pre-counted
}

__global__ void k_hist(const int* __restrict__ ei, int E) {
    int i = blockIdx.x * blockDim.x + threadIdx.x;
    if (i >= E) return;
    atomicAdd(&g_cnt[ei[E + i]], 1);
}

// per-block sum of 1024 degrees
__global__ void k_bsum() {
    __shared__ int sh[1024];
    int b = blockIdx.x, t = threadIdx.x, i = b * 1024 + t;
    sh[t] = (i < NN) ? g_cnt[i] : 0;
    __syncthreads();
    for (int off = 512; off; off >>= 1) {
        if (t < off) sh[t] += sh[t + off];
        __syncthreads();
    }
    if (t == 0) g_bsum[b] = sh[0];
}

// tiny scan of 98 block sums (smem-serial, no global latency in the loop)
__global__ void k_bscan(int etot) {
    __shared__ int s[NB];
    int t = threadIdx.x;
    if (t < NB) s[t] = g_bsum[t];
    __syncthreads();
    if (t == 0) {
        int run = 0;
        for (int b = 0; b < NB; b++) { int v = s[b]; s[b] = run; run += v; }
    }
    __syncthreads();
    if (t < NB) g_boff[t] = s[t];
    if (t == 0) g_rp[NN] = etot;
}

// per-block Hillis-Steele scan -> rp/fill; self-loop placed at row start.
__global__ void k_rp() {
    __shared__ int sh[1024];
    int b = blockIdx.x, t = threadIdx.x, i = b * 1024 + t;
    int v = (i < NN) ? g_cnt[i] : 0;
    sh[t] = v;
    __syncthreads();
    for (int off = 1; off < 1024; off <<= 1) {
        int cur = sh[t];
        int u = (t >= off) ? sh[t - off] : 0;
        __syncthreads();
        sh[t] = cur + u;
        __syncthreads();
    }
    if (i < NN) {
        int rp = g_boff[b] + sh[t] - v;    // exclusive
        g_rp[i]   = rp;
        g_fill[i] = rp + 1;                // slot 0 = self loop
        g_csr[rp] = i;
    }
}

__global__ void k_scatter(const int* __restrict__ ei, int E) {
    int i = blockIdx.x * blockDim.x + threadIdx.x;
    if (i >= E) return;
    int s = ei[i], d = ei[E + i];
    int pos = atomicAdd(&g_fill[d], 1);
    g_csr[pos] = s;
}

// ---------------- GEMM1 + attention projections fused (persistent) -----------
#define GEMM_BLOCKS 1184
__global__ void k_gemm1(const float* __restrict__ x, const float* __restrict__ W,
                        const float* __restrict__ as, const float* __restrict__ ad) {
    __shared__ float sW[64 * 64];
    __shared__ float sx[256];
    __shared__ float ss[64], sd[64];
    int t = threadIdx.x;
#pragma unroll
    for (int i = 0; i < 16; i++) sW[i * 256 + t] = W[i * 256 + t];
    if (t < 64) { ss[t] = as[t]; sd[t] = ad[t]; }
    int ln = t >> 6, c = t & 63;
    int lane = t & 31, warp = t >> 5;
    int half = warp & 1;

    for (int tile = blockIdx.x; tile < NN / 4; tile += GEMM_BLOCKS) {
        int n0 = tile * 4;
        __syncthreads();
        sx[t] = x[n0 * 64 + t];
        __syncthreads();
        const float* xr = &sx[ln * 64];
        float acc = 0.f;
#pragma unroll
        for (int k = 0; k < 64; k++) acc = fmaf(xr[k], sW[k * 64 + c], acc);
        g_h1[(n0 + ln) * 64 + c] = acc;

        float ps = acc * ss[c], pd = acc * sd[c];
#pragma unroll
        for (int off = 8; off; off >>= 1) {
            ps += __shfl_down_sync(0xffffffffu, ps, off, 16);
            pd += __shfl_down_sync(0xffffffffu, pd, off, 16);
        }
        int node = n0 + (warp >> 1);
        float* asn = (float*)&g_as1[node];
        float* adn = (float*)&g_ad1[node];
        if (lane == 0)  { asn[half * 2]     = ps; adn[half * 2]     = pd; }
        if (lane == 16) { asn[half * 2 + 1] = ps; adn[half * 2 + 1] = pd; }
    }
}

// ---------------- layer1 aggregation: warp per dst, no max pass, no atomics ---
__global__ void k_agg1(const float* __restrict__ b1, const float* __restrict__ W2,
                       const float* __restrict__ as2p, const float* __restrict__ ad2p) {
    __shared__ int    ssrc[8][32];
    __shared__ float4 se[8][32];
    int lane = threadIdx.x & 31, w = threadIdx.x >> 5;
    int d = blockIdx.x * 8 + w;
    if (d >= NN) return;
    int base = g_rp[d];
    int deg  = g_rp[d + 1] - base;
    float4 ad = g_ad1[d];

    int hl = lane >> 4;
    float accL = 0.f, accH = 0.f;
    float d0 = 0.f, d1 = 0.f, d2 = 0.f, d3 = 0.f;

    for (int chunk = 0; chunk < deg; chunk += 32) {
        int i = chunk + lane;
        int s = 0;
        float4 e = make_float4(0.f, 0.f, 0.f, 0.f);
        if (i < deg) {
            s = g_csr[base + i];
            float4 a = g_as1[s];
            e.x = __expf(lrelu(a.x + ad.x)); d0 += e.x;
            e.y = __expf(lrelu(a.y + ad.y)); d1 += e.y;
            e.z = __expf(lrelu(a.z + ad.z)); d2 += e.z;
            e.w = __expf(lrelu(a.w + ad.w)); d3 += e.w;
        }
        __syncwarp();
        ssrc[w][lane] = s;
        se[w][lane]   = e;
        __syncwarp();
        int cnt = deg - chunk; if (cnt > 32) cnt = 32;
        int j = 0;
        for (; j + 4 <= cnt; j += 4) {
            int s0 = ssrc[w][j], s1 = ssrc[w][j + 1], s2 = ssrc[w][j + 2], s3 = ssrc[w][j + 3];
            const float* h0 = &g_h1[s0 * 64];
            const float* h1p = &g_h1[s1 * 64];
            const float* h2p = &g_h1[s2 * 64];
            const float* h3p = &g_h1[s3 * 64];
            float a0 = h0[lane],  b0 = h0[lane + 32];
            float a1 = h1p[lane], b1v = h1p[lane + 32];
            float a2 = h2p[lane], b2v = h2p[lane + 32];
            float a3 = h3p[lane], b3v = h3p[lane + 32];
            float4 E0 = se[w][j], E1 = se[w][j + 1], E2 = se[w][j + 2], E3 = se[w][j + 3];
            accL = fmaf(a0, hl ? E0.y : E0.x, accL);
            accH = fmaf(b0, hl ? E0.w : E0.z, accH);
            accL = fmaf(a1, hl ? E1.y : E1.x, accL);
            accH = fmaf(b1v, hl ? E1.w : E1.z, accH);
            accL = fmaf(a2, hl ? E2.y : E2.x, accL);
            accH = fmaf(b2v, hl ? E2.w : E2.z, accH);
            accL = fmaf(a3, hl ? E3.y : E3.x, accL);
            accH = fmaf(b3v, hl ? E3.w : E3.z, accH);
        }
        for (; j < cnt; j++) {
            int sj = ssrc[w][j];
            float4 E = se[w][j];
            const float* hr = &g_h1[sj * 64];
            accL = fmaf(hr[lane],      hl ? E.y : E.x, accL);
            accH = fmaf(hr[lane + 32], hl ? E.w : E.z, accH);
        }
    }
#pragma unroll
    for (int off = 16; off; off >>= 1) {
        d0 += __shfl_xor_sync(0xffffffffu, d0, off);
        d1 += __shfl_xor_sync(0xffffffffu, d1, off);
        d2 += __shfl_xor_sync(0xffffffffu, d2, off);
        d3 += __shfl_xor_sync(0xffffffffu, d3, off);
    }

    float denL = (hl ? d1 : d0) + EPSV;
    float denH = (hl ? d3 : d2) + EPSV;
    float v1 = accL / denL + b1[lane];
    float v2 = accH / denH + b1[lane + 32];
    v1 = v1 > 0.f ? v1 : (__expf(v1) - 1.f);
    v2 = v2 > 0.f ? v2 : (__expf(v2) - 1.f);
    float h2 = v1 * W2[lane] + v2 * W2[lane + 32];
#pragma unroll
    for (int off = 16; off; off >>= 1) h2 += __shfl_xor_sync(0xffffffffu, h2, off);
    if (lane == 0) {
        g_sh2[d] = make_float2(h2 * as2p[0], h2);
        g_ad2[d] = h2 * ad2p[0];
    }
}

// ---------------- layer2 aggregation + final output ---------------------------
__global__ void k_agg2(float* __restrict__ out, const float* __restrict__ b2) {
    int lane = threadIdx.x & 31, warp = threadIdx.x >> 5;
    int d = blockIdx.x * 8 + warp;
    if (d >= NN) return;
    int base = g_rp[d];
    int deg  = g_rp[d + 1] - base;
    float adv = g_ad2[d];

    float num = 0.f, den = 0.f;
    for (int i = lane; i < deg; i += 32) {
        int s = g_csr[base + i];
        float2 sh = g_sh2[s];
        float e = __expf(lrelu(sh.x + adv));
        num = fmaf(e, sh.y, num);
        den += e;
    }
#pragma unroll
    for (int off = 16; off; off >>= 1) {
        num += __shfl_xor_sync(0xffffffffu, num, off);
        den += __shfl_xor_sync(0xffffffffu, den, off);
    }
    if (lane == 0) out[d] = num / (den + EPSV) + b2[0];
}

// ---------------- launch -----------------------------------------------------
extern "C" void kernel_launch(void* const* d_in, const int* in_sizes, int n_in,
                              void* d_out, int out_size) {
    const float* x    = (const float*)d_in[0];
    const int*   ei   = (const int*)d_in[1];
    const float* W1   = (const float*)d_in[2];
    const float* as1  = (const float*)d_in[3];
    const float* ad1  = (const float*)d_in[4];
    const float* b1   = (const float*)d_in[5];
    const float* W2   = (const float*)d_in[6];
    const float* as2  = (const float*)d_in[7];
    const float* ad2  = (const float*)d_in[8];
    const float* b2   = (const float*)d_in[9];
    float*       out  = (float*)d_out;

    int E    = in_sizes[1] / 2;
    int etot = E + NN;
    int eb   = (E + 255) / 256;

    k_zero   <<<(NN + 255) / 256, 256>>>();
    k_hist   <<<eb, 256>>>(ei, E);
    k_bsum   <<<NB, 1024>>>();
    k_bscan  <<<1, 128>>>(etot);
    k_rp     <<<NB, 1024>>>();
    k_scatter<<<eb, 256>>>(ei, E);
    k_gemm1  <<<GEMM_BLOCKS, 256>>>(x, W1, as1, ad1);
    k_agg1   <<<NN / 8, 256>>>(b1, W2, as2, ad2);
    k_agg2   <<<NN / 8, 256>>>(out, b2);
}

// round 6
// speedup vs baseline: 2.4619x; 1.1029x over previous
#include <cuda_runtime.h>
#include <cuda_fp16.h>

#define NN      100000
#define ET_MAX  1700000
#define NEG     0.2f
#define EPSV    1e-16f
#define NB      98              // ceil(NN/1024)

// ---------------- scratch ----------------------------------------------------
__device__ __align__(128) __half g_h1h[NN * 64];   // h1 [N,64] fp16 (12.8MB, 1 line/row)
__device__ float4 g_as1[NN];          // per-node a_src, 4 heads (fp32)
__device__ float4 g_ad1[NN];          // per-node a_dst, 4 heads
__device__ int    g_cnt[NN];
__device__ int    g_rp[NN + 1];
__device__ int    g_fill[NN];
__device__ int    g_csr[ET_MAX];
__device__ int    g_bsum[NB];
__device__ int    g_boff[NB];
__device__ float2 g_sh2[NN];          // packed {a_src2, h2}
__device__ float  g_ad2[NN];

__device__ __forceinline__ float lrelu(float a) { return a > 0.f ? a : NEG * a; }

// ---------------- CSR build (all coalesced) ----------------------------------
__global__ void k_zero() {
    int i = blockIdx.x * blockDim.x + threadIdx.x;
    if (i < NN) g_cnt[i] = 1;          // self-loop pre-counted
}

__global__ void k_hist(const int* __restrict__ ei, int E) {
    int i = blockIdx.x * blockDim.x + threadIdx.x;
    if (i >= E) return;
    atomicAdd(&g_cnt[ei[E + i]], 1);
}

__global__ void k_bsum() {
    __shared__ int sh[1024];
    int b = blockIdx.x, t = threadIdx.x, i = b * 1024 + t;
    sh[t] = (i < NN) ? g_cnt[i] : 0;
    __syncthreads();
    for (int off = 512; off; off >>= 1) {
        if (t < off) sh[t] += sh[t + off];
        __syncthreads();
    }
    if (t == 0) g_bsum[b] = sh[0];
}

__global__ void k_bscan(int etot) {
    __shared__ int s[NB];
    int t = threadIdx.x;
    if (t < NB) s[t] = g_bsum[t];
    __syncthreads();
    if (t == 0) {
        int run = 0;
        for (int b = 0; b < NB; b++) { int v = s[b]; s[b] = run; run += v; }
    }
    __syncthreads();
    if (t < NB) g_boff[t] = s[t];
    if (t == 0) g_rp[NN] = etot;
}

__global__ void k_rp() {
    __shared__ int sh[1024];
    int b = blockIdx.x, t = threadIdx.x, i = b * 1024 + t;
    int v = (i < NN) ? g_cnt[i] : 0;
    sh[t] = v;
    __syncthreads();
    for (int off = 1; off < 1024; off <<= 1) {
        int cur = sh[t];
        int u = (t >= off) ? sh[t - off] : 0;
        __syncthreads();
        sh[t] = cur + u;
        __syncthreads();
    }
    if (i < NN) {
        int rp = g_boff[b] + sh[t] - v;    // exclusive
        g_rp[i]   = rp;
        g_fill[i] = rp + 1;                // slot 0 = self loop
        g_csr[rp] = i;
    }
}

__global__ void k_scatter(const int* __restrict__ ei, int E) {
    int i = blockIdx.x * blockDim.x + threadIdx.x;
    if (i >= E) return;
    int s = ei[i], d = ei[E + i];
    int pos = atomicAdd(&g_fill[d], 1);
    g_csr[pos] = s;
}

// ---------------- GEMM1 + attention projections fused (persistent) -----------
#define GEMM_BLOCKS 1184
__global__ void k_gemm1(const float* __restrict__ x, const float* __restrict__ W,
                        const float* __restrict__ as, const float* __restrict__ ad) {
    __shared__ float sW[64 * 64];
    __shared__ float sx[256];
    __shared__ float ss[64], sd[64];
    int t = threadIdx.x;
#pragma unroll
    for (int i = 0; i < 16; i++) sW[i * 256 + t] = W[i * 256 + t];
    if (t < 64) { ss[t] = as[t]; sd[t] = ad[t]; }
    int ln = t >> 6, c = t & 63;
    int lane = t & 31, warp = t >> 5;
    int half = warp & 1;

    for (int tile = blockIdx.x; tile < NN / 4; tile += GEMM_BLOCKS) {
        int n0 = tile * 4;
        __syncthreads();
        sx[t] = x[n0 * 64 + t];
        __syncthreads();
        const float* xr = &sx[ln * 64];
        float a0 = 0.f, a1 = 0.f, a2 = 0.f, a3 = 0.f;
#pragma unroll
        for (int k = 0; k < 64; k += 4) {
            a0 = fmaf(xr[k],     sW[k * 64 + c],       a0);
            a1 = fmaf(xr[k + 1], sW[(k + 1) * 64 + c], a1);
            a2 = fmaf(xr[k + 2], sW[(k + 2) * 64 + c], a2);
            a3 = fmaf(xr[k + 3], sW[(k + 3) * 64 + c], a3);
        }
        float acc = (a0 + a1) + (a2 + a3);
        g_h1h[(n0 + ln) * 64 + c] = __float2half(acc);

        float ps = acc * ss[c], pd = acc * sd[c];
#pragma unroll
        for (int off = 8; off; off >>= 1) {
            ps += __shfl_down_sync(0xffffffffu, ps, off, 16);
            pd += __shfl_down_sync(0xffffffffu, pd, off, 16);
        }
        int node = n0 + (warp >> 1);
        float* asn = (float*)&g_as1[node];
        float* adn = (float*)&g_ad1[node];
        if (lane == 0)  { asn[half * 2]     = ps; adn[half * 2]     = pd; }
        if (lane == 16) { asn[half * 2 + 1] = ps; adn[half * 2 + 1] = pd; }
    }
}

// ---------------- layer1 aggregation: warp per dst, fp16 gather ----------------
__global__ void k_agg1(const float* __restrict__ b1, const float* __restrict__ W2,
                       const float* __restrict__ as2p, const float* __restrict__ ad2p) {
    __shared__ int   ssrc[8][32];
    __shared__ float seT[8][4][33];            // [warp][head][edge], pad 33
    int lane = threadIdx.x & 31, w = threadIdx.x >> 5;
    int d = blockIdx.x * 8 + w;
    if (d >= NN) return;
    int base = g_rp[d];
    int deg  = g_rp[d + 1] - base;
    float4 ad = g_ad1[d];

    int hh = lane >> 3;                         // head of channels 2l,2l+1
    float acc0 = 0.f, acc1 = 0.f;
    float d0 = 0.f, d1 = 0.f, d2 = 0.f, d3 = 0.f;

    for (int chunk = 0; chunk < deg; chunk += 32) {
        int i = chunk + lane;
        int s = 0;
        float e0 = 0.f, e1 = 0.f, e2 = 0.f, e3 = 0.f;
        if (i < deg) {
            s = g_csr[base + i];
            float4 a = g_as1[s];
            e0 = __expf(lrelu(a.x + ad.x)); d0 += e0;
            e1 = __expf(lrelu(a.y + ad.y)); d1 += e1;
            e2 = __expf(lrelu(a.z + ad.z)); d2 += e2;
            e3 = __expf(lrelu(a.w + ad.w)); d3 += e3;
        }
        __syncwarp();
        ssrc[w][lane] = s;
        seT[w][0][lane] = e0; seT[w][1][lane] = e1;
        seT[w][2][lane] = e2; seT[w][3][lane] = e3;
        __syncwarp();
        int cnt = deg - chunk; if (cnt > 32) cnt = 32;
        int j = 0;
        for (; j + 8 <= cnt; j += 8) {
            __half2 v[8]; float ew[8];
#pragma unroll
            for (int k = 0; k < 8; k++) {
                int sj = ssrc[w][j + k];
                v[k]  = ((const __half2*)(g_h1h + sj * 64))[lane];
                ew[k] = seT[w][hh][j + k];
            }
#pragma unroll
            for (int k = 0; k < 8; k++) {
                float2 f = __half22float2(v[k]);
                acc0 = fmaf(f.x, ew[k], acc0);
                acc1 = fmaf(f.y, ew[k], acc1);
            }
        }
        for (; j < cnt; j++) {
            int sj = ssrc[w][j];
            __half2 vv = ((const __half2*)(g_h1h + sj * 64))[lane];
            float ew = seT[w][hh][j];
            float2 f = __half22float2(vv);
            acc0 = fmaf(f.x, ew, acc0);
            acc1 = fmaf(f.y, ew, acc1);
        }
    }
#pragma unroll
    for (int off = 16; off; off >>= 1) {
        d0 += __shfl_xor_sync(0xffffffffu, d0, off);
        d1 += __shfl_xor_sync(0xffffffffu, d1, off);
        d2 += __shfl_xor_sync(0xffffffffu, d2, off);
        d3 += __shfl_xor_sync(0xffffffffu, d3, off);
    }

    // epilogue: out1 = elu(num/den + b1); h2 = out1.W2; layer-2 projections
    float den = (hh == 0 ? d0 : hh == 1 ? d1 : hh == 2 ? d2 : d3) + EPSV;
    float2 bb = ((const float2*)b1)[lane];
    float2 ww = ((const float2*)W2)[lane];
    float v0 = acc0 / den + bb.x;
    float v1 = acc1 / den + bb.y;
    v0 = v0 > 0.f ? v0 : (__expf(v0) - 1.f);
    v1 = v1 > 0.f ? v1 : (__expf(v1) - 1.f);
    float h2 = v0 * ww.x + v1 * ww.y;
#pragma unroll
    for (int off = 16; off; off >>= 1) h2 += __shfl_xor_sync(0xffffffffu, h2, off);
    if (lane == 0) {
        g_sh2[d] = make_float2(h2 * as2p[0], h2);
        g_ad2[d] = h2 * ad2p[0];
    }
}

// ---------------- layer2 aggregation + final output ---------------------------
__global__ void k_agg2(float* __restrict__ out, const float* __restrict__ b2) {
    int lane = threadIdx.x & 31, warp = threadIdx.x >> 5;
    int d = blockIdx.x * 8 + warp;
    if (d >= NN) return;
    int base = g_rp[d];
    int deg  = g_rp[d + 1] - base;
    float adv = g_ad2[d];

    float num = 0.f, den = 0.f;
    for (int i = lane; i < deg; i += 32) {
        int s = g_csr[base + i];
        float2 sh = g_sh2[s];
        float e = __expf(lrelu(sh.x + adv));
        num = fmaf(e, sh.y, num);
        den += e;
    }
#pragma unroll
    for (int off = 16; off; off >>= 1) {
        num += __shfl_xor_sync(0xffffffffu, num, off);
        den += __shfl_xor_sync(0xffffffffu, den, off);
    }
    if (lane == 0) out[d] = num / (den + EPSV) + b2[0];
}

// ---------------- launch -----------------------------------------------------
extern "C" void kernel_launch(void* const* d_in, const int* in_sizes, int n_in,
                              void* d_out, int out_size) {
    const float* x    = (const float*)d_in[0];
    const int*   ei   = (const int*)d_in[1];
    const float* W1   = (const float*)d_in[2];
    const float* as1  = (const float*)d_in[3];
    const float* ad1  = (const float*)d_in[4];
    const float* b1   = (const float*)d_in[5];
    const float* W2   = (const float*)d_in[6];
    const float* as2  = (const float*)d_in[7];
    const float* ad2  = (const float*)d_in[8];
    const float* b2   = (const float*)d_in[9];
    float*       out  = (float*)d_out;

    int E    = in_sizes[1] / 2;
    int etot = E + NN;
    int eb   = (E + 255) / 256;

    k_zero   <<<(NN + 255) / 256, 256>>>();
    k_hist   <<<eb, 256>>>(ei, E);
    k_bsum   <<<NB, 1024>>>();
    k_gemm1  <<<GEMM_BLOCKS, 256>>>(x, W1, as1, ad1);   // idx 3: ncu capture target
    k_bscan  <<<1, 128>>>(etot);
    k_rp     <<<NB, 1024>>>();
    k_scatter<<<eb, 256>>>(ei, E);
    k_agg1   <<<NN / 8, 256>>>(b1, W2, as2, ad2);
    k_agg2   <<<NN / 8, 256>>>(out, b2);
}

// round 7
// speedup vs baseline: 3.3007x; 1.3407x over previous
#include <cuda_runtime.h>
#include <cuda_fp16.h>

#define NN      100000
#define ET_MAX  1700000
#define NEG     0.2f
#define EPSV    1e-16f
#define NB      98              // ceil(NN/1024)

// ---------------- scratch ----------------------------------------------------
__device__ __align__(128) __half g_h1h[NN * 64];   // h1 [N,64] fp16 (12.8MB, 1 line/row)
__device__ float4 g_as1[NN];          // per-node a_src, 4 heads (fp32)
__device__ float4 g_ad1[NN];          // per-node a_dst, 4 heads
__device__ int    g_cnt[NN];
__device__ int    g_rp[NN + 1];
__device__ int    g_fill[NN];
__device__ int    g_csr[ET_MAX];
__device__ int    g_bsum[NB];
__device__ int    g_boff[NB];
__device__ float2 g_sh2[NN];          // packed {a_src2, h2}
__device__ float  g_ad2[NN];

__device__ __forceinline__ float lrelu(float a) { return a > 0.f ? a : NEG * a; }

// ---------------- CSR build (all coalesced) ----------------------------------
__global__ void k_zero() {
    int i = blockIdx.x * blockDim.x + threadIdx.x;
    if (i < NN) g_cnt[i] = 1;          // self-loop pre-counted
}

__global__ void k_hist(const int* __restrict__ ei, int E) {
    int i = blockIdx.x * blockDim.x + threadIdx.x;
    if (i >= E) return;
    atomicAdd(&g_cnt[ei[E + i]], 1);
}

__global__ void k_bsum() {
    __shared__ int sh[1024];
    int b = blockIdx.x, t = threadIdx.x, i = b * 1024 + t;
    sh[t] = (i < NN) ? g_cnt[i] : 0;
    __syncthreads();
    for (int off = 512; off; off >>= 1) {
        if (t < off) sh[t] += sh[t + off];
        __syncthreads();
    }
    if (t == 0) g_bsum[b] = sh[0];
}

__global__ void k_bscan(int etot) {
    __shared__ int s[NB];
    int t = threadIdx.x;
    if (t < NB) s[t] = g_bsum[t];
    __syncthreads();
    if (t == 0) {
        int run = 0;
        for (int b = 0; b < NB; b++) { int v = s[b]; s[b] = run; run += v; }
    }
    __syncthreads();
    if (t < NB) g_boff[t] = s[t];
    if (t == 0) g_rp[NN] = etot;
}

__global__ void k_rp() {
    __shared__ int sh[1024];
    int b = blockIdx.x, t = threadIdx.x, i = b * 1024 + t;
    int v = (i < NN) ? g_cnt[i] : 0;
    sh[t] = v;
    __syncthreads();
    for (int off = 1; off < 1024; off <<= 1) {
        int cur = sh[t];
        int u = (t >= off) ? sh[t - off] : 0;
        __syncthreads();
        sh[t] = cur + u;
        __syncthreads();
    }
    if (i < NN) {
        int rp = g_boff[b] + sh[t] - v;    // exclusive
        g_rp[i]   = rp;
        g_fill[i] = rp + 1;                // slot 0 = self loop
        g_csr[rp] = i;
    }
}

__global__ void k_scatter(const int* __restrict__ ei, int E) {
    int i = blockIdx.x * blockDim.x + threadIdx.x;
    if (i >= E) return;
    int s = ei[i], d = ei[E + i];
    int pos = atomicAdd(&g_fill[d], 1);
    g_csr[pos] = s;
}

// ---------------- GEMM1 + attention projections, register-tiled --------------
// 32 nodes per tile; thread = 2 rows x 4 cols micro-tile. Persistent.
#define GEMM_BLOCKS 1184
#define NTILES      (NN / 32)          // 3125
__global__ void k_gemm1(const float* __restrict__ x, const float* __restrict__ W,
                        const float* __restrict__ as, const float* __restrict__ ad) {
    __shared__ float4 sW4[64 * 16];    // sW4[k*16+ci] = W[k][4ci..4ci+3]
    __shared__ float  sx[32 * 64];     // 32 node rows
    __shared__ float  ss[64], sd[64];
    int t = threadIdx.x;
    for (int i = t; i < 1024; i += 256) sW4[i] = ((const float4*)W)[i];
    if (t < 64) { ss[t] = as[t]; sd[t] = ad[t]; }
    int lane = t & 31, w = t >> 5;
    int ci = lane & 15, half = lane >> 4;
    int rgl = w * 2 + half;            // row-group 0..15 (2 rows each)

    for (int tile = blockIdx.x; tile < NTILES; tile += GEMM_BLOCKS) {
        __syncthreads();
        const float4* xg = (const float4*)(x + tile * 32 * 64);
        ((float4*)sx)[t]       = xg[t];
        ((float4*)sx)[t + 256] = xg[t + 256];
        __syncthreads();

        const float* x0 = &sx[(rgl * 2) * 64];
        const float* x1 = &sx[(rgl * 2 + 1) * 64];
        float a00 = 0.f, a01 = 0.f, a02 = 0.f, a03 = 0.f;
        float a10 = 0.f, a11 = 0.f, a12 = 0.f, a13 = 0.f;
#pragma unroll
        for (int k = 0; k < 64; k += 4) {
            float4 xa = *(const float4*)(x0 + k);
            float4 xb = *(const float4*)(x1 + k);
#pragma unroll
            for (int kk = 0; kk < 4; kk++) {
                float4 wv = sW4[(k + kk) * 16 + ci];
                float xav = (&xa.x)[kk], xbv = (&xb.x)[kk];
                a00 = fmaf(xav, wv.x, a00); a01 = fmaf(xav, wv.y, a01);
                a02 = fmaf(xav, wv.z, a02); a03 = fmaf(xav, wv.w, a03);
                a10 = fmaf(xbv, wv.x, a10); a11 = fmaf(xbv, wv.y, a11);
                a12 = fmaf(xbv, wv.z, a12); a13 = fmaf(xbv, wv.w, a13);
            }
        }
        int n0 = tile * 32 + rgl * 2;
        // store h1 fp16: 4 cols = one uint2 (8B) per row
        {
            __half2 p0 = __floats2half2_rn(a00, a01);
            __half2 p1 = __floats2half2_rn(a02, a03);
            __half2* hp = (__half2*)(g_h1h + (size_t)n0 * 64 + 4 * ci);
            hp[0] = p0; hp[1] = p1;
            __half2 q0 = __floats2half2_rn(a10, a11);
            __half2 q1 = __floats2half2_rn(a12, a13);
            __half2* hq = (__half2*)(g_h1h + (size_t)(n0 + 1) * 64 + 4 * ci);
            hq[0] = q0; hq[1] = q1;
        }
        // attention projections: head = ci>>2 (cols 16h..16h+15 = ci in [4h,4h+4))
        float s0 = a00 * ss[4 * ci] + a01 * ss[4 * ci + 1] + a02 * ss[4 * ci + 2] + a03 * ss[4 * ci + 3];
        float d0v = a00 * sd[4 * ci] + a01 * sd[4 * ci + 1] + a02 * sd[4 * ci + 2] + a03 * sd[4 * ci + 3];
        float s1 = a10 * ss[4 * ci] + a11 * ss[4 * ci + 1] + a12 * ss[4 * ci + 2] + a13 * ss[4 * ci + 3];
        float d1v = a10 * sd[4 * ci] + a11 * sd[4 * ci + 1] + a12 * sd[4 * ci + 2] + a13 * sd[4 * ci + 3];
#pragma unroll
        for (int off = 1; off <= 2; off <<= 1) {
            s0  += __shfl_xor_sync(0xffffffffu, s0, off);
            d0v += __shfl_xor_sync(0xffffffffu, d0v, off);
            s1  += __shfl_xor_sync(0xffffffffu, s1, off);
            d1v += __shfl_xor_sync(0xffffffffu, d1v, off);
        }
        if ((ci & 3) == 0) {
            int head = ci >> 2;
            ((float*)&g_as1[n0])[head]     = s0;
            ((float*)&g_ad1[n0])[head]     = d0v;
            ((float*)&g_as1[n0 + 1])[head] = s1;
            ((float*)&g_ad1[n0 + 1])[head] = d1v;
        }
    }
}

// ---------------- layer1 aggregation: warp per dst, fp16 gather ----------------
__global__ void k_agg1(const float* __restrict__ b1, const float* __restrict__ W2,
                       const float* __restrict__ as2p, const float* __restrict__ ad2p) {
    __shared__ int   ssrc[8][32];
    __shared__ float seT[8][4][33];            // [warp][head][edge], pad 33
    int lane = threadIdx.x & 31, w = threadIdx.x >> 5;
    int d = blockIdx.x * 8 + w;
    if (d >= NN) return;
    int base = g_rp[d];
    int deg  = g_rp[d + 1] - base;
    float4 ad = g_ad1[d];

    int hh = lane >> 3;                         // head of channels 2l,2l+1
    float acc0 = 0.f, acc1 = 0.f;
    float d0 = 0.f, d1 = 0.f, d2 = 0.f, d3 = 0.f;

    for (int chunk = 0; chunk < deg; chunk += 32) {
        int i = chunk + lane;
        int s = 0;
        float e0 = 0.f, e1 = 0.f, e2 = 0.f, e3 = 0.f;
        if (i < deg) {
            s = g_csr[base + i];
            float4 a = g_as1[s];
            e0 = __expf(lrelu(a.x + ad.x)); d0 += e0;
            e1 = __expf(lrelu(a.y + ad.y)); d1 += e1;
            e2 = __expf(lrelu(a.z + ad.z)); d2 += e2;
            e3 = __expf(lrelu(a.w + ad.w)); d3 += e3;
        }
        __syncwarp();
        ssrc[w][lane] = s;
        seT[w][0][lane] = e0; seT[w][1][lane] = e1;
        seT[w][2][lane] = e2; seT[w][3][lane] = e3;
        __syncwarp();
        int cnt = deg - chunk; if (cnt > 32) cnt = 32;
        int j = 0;
        for (; j + 8 <= cnt; j += 8) {
            __half2 v[8]; float ew[8];
#pragma unroll
            for (int k = 0; k < 8; k++) {
                int sj = ssrc[w][j + k];
                v[k]  = ((const __half2*)(g_h1h + (size_t)sj * 64))[lane];
                ew[k] = seT[w][hh][j + k];
            }
#pragma unroll
            for (int k = 0; k < 8; k++) {
                float2 f = __half22float2(v[k]);
                acc0 = fmaf(f.x, ew[k], acc0);
                acc1 = fmaf(f.y, ew[k], acc1);
            }
        }
        for (; j < cnt; j++) {
            int sj = ssrc[w][j];
            __half2 vv = ((const __half2*)(g_h1h + (size_t)sj * 64))[lane];
            float ew = seT[w][hh][j];
            float2 f = __half22float2(vv);
            acc0 = fmaf(f.x, ew, acc0);
            acc1 = fmaf(f.y, ew, acc1);
        }
    }
#pragma unroll
    for (int off = 16; off; off >>= 1) {
        d0 += __shfl_xor_sync(0xffffffffu, d0, off);
        d1 += __shfl_xor_sync(0xffffffffu, d1, off);
        d2 += __shfl_xor_sync(0xffffffffu, d2, off);
        d3 += __shfl_xor_sync(0xffffffffu, d3, off);
    }

    float den = (hh == 0 ? d0 : hh == 1 ? d1 : hh == 2 ? d2 : d3) + EPSV;
    float2 bb = ((const float2*)b1)[lane];
    float2 ww = ((const float2*)W2)[lane];
    float v0 = acc0 / den + bb.x;
    float v1 = acc1 / den + bb.y;
    v0 = v0 > 0.f ? v0 : (__expf(v0) - 1.f);
    v1 = v1 > 0.f ? v1 : (__expf(v1) - 1.f);
    float h2 = v0 * ww.x + v1 * ww.y;
#pragma unroll
    for (int off = 16; off; off >>= 1) h2 += __shfl_xor_sync(0xffffffffu, h2, off);
    if (lane == 0) {
        g_sh2[d] = make_float2(h2 * as2p[0], h2);
        g_ad2[d] = h2 * ad2p[0];
    }
}

// ---------------- layer2 aggregation + final output ---------------------------
__global__ void k_agg2(float* __restrict__ out, const float* __restrict__ b2) {
    int lane = threadIdx.x & 31, warp = threadIdx.x >> 5;
    int d = blockIdx.x * 8 + warp;
    if (d >= NN) return;
    int base = g_rp[d];
    int deg  = g_rp[d + 1] - base;
    float adv = g_ad2[d];

    float num = 0.f, den = 0.f;
    for (int i = lane; i < deg; i += 32) {
        int s = g_csr[base + i];
        float2 sh = g_sh2[s];
        float e = __expf(lrelu(sh.x + adv));
        num = fmaf(e, sh.y, num);
        den += e;
    }
#pragma unroll
    for (int off = 16; off; off >>= 1) {
        num += __shfl_xor_sync(0xffffffffu, num, off);
        den += __shfl_xor_sync(0xffffffffu, den, off);
    }
    if (lane == 0) out[d] = num / (den + EPSV) + b2[0];
}

// ---------------- launch -----------------------------------------------------
extern "C" void kernel_launch(void* const* d_in, const int* in_sizes, int n_in,
                              void* d_out, int out_size) {
    const float* x    = (const float*)d_in[0];
    const int*   ei   = (const int*)d_in[1];
    const float* W1   = (const float*)d_in[2];
    const float* as1  = (const float*)d_in[3];
    const float* ad1  = (const float*)d_in[4];
    const float* b1   = (const float*)d_in[5];
    const float* W2   = (const float*)d_in[6];
    const float* as2  = (const float*)d_in[7];
    const float* ad2  = (const float*)d_in[8];
    const float* b2   = (const float*)d_in[9];
    float*       out  = (float*)d_out;

    int E    = in_sizes[1] / 2;
    int etot = E + NN;
    int eb   = (E + 255) / 256;

    k_zero   <<<(NN + 255) / 256, 256>>>();
    k_hist   <<<eb, 256>>>(ei, E);
    k_bsum   <<<NB, 1024>>>();
    k_gemm1  <<<GEMM_BLOCKS, 256>>>(x, W1, as1, ad1);   // idx 3: ncu capture target
    k_bscan  <<<1, 128>>>(etot);
    k_rp     <<<NB, 1024>>>();
    k_scatter<<<eb, 256>>>(ei, E);
    k_agg1   <<<NN / 8, 256>>>(b1, W2, as2, ad2);
    k_agg2   <<<NN / 8, 256>>>(out, b2);
}

// round 8
// speedup vs baseline: 3.5490x; 1.0752x over previous
#include <cuda_runtime.h>
#include <cuda_fp16.h>

#define NN      100000
#define ET_MAX  1700000
#define NEG     0.2f
#define EPSV    1e-16f
#define NB      98              // ceil(NN/1024)

// ---------------- scratch ----------------------------------------------------
__device__ __align__(128) __half g_h1h[NN * 64];   // h1 [N,64] fp16 (12.8MB, 1 line/row)
__device__ float4 g_as1[NN];          // per-node a_src, 4 heads (fp32)
__device__ float4 g_ad1[NN];          // per-node a_dst, 4 heads
__device__ int    g_cnt[NN];
__device__ int    g_rp[NN + 1];
__device__ int    g_fill[NN];
__device__ int    g_csr[ET_MAX];
__device__ int    g_bsum[NB];
__device__ int    g_boff[NB];
__device__ float2 g_sh2[NN];          // packed {a_src2, h2}
__device__ float  g_ad2[NN];

__device__ __forceinline__ float lrelu(float a) { return a > 0.f ? a : NEG * a; }

// ---------------- CSR build (all coalesced) ----------------------------------
__global__ void k_zero() {
    int i = blockIdx.x * blockDim.x + threadIdx.x;
    if (i < NN) g_cnt[i] = 1;          // self-loop pre-counted
}

// 4 edges per thread, int4 loads, 4 independent atomics in flight.
__global__ void k_hist(const int* __restrict__ ei, int E) {
    int i0 = (blockIdx.x * blockDim.x + threadIdx.x) * 4;
    if (i0 >= E) return;
    int4 d4 = *(const int4*)(ei + E + i0);
    atomicAdd(&g_cnt[d4.x], 1);
    atomicAdd(&g_cnt[d4.y], 1);
    atomicAdd(&g_cnt[d4.z], 1);
    atomicAdd(&g_cnt[d4.w], 1);
}

__global__ void k_bsum() {
    __shared__ int sh[1024];
    int b = blockIdx.x, t = threadIdx.x, i = b * 1024 + t;
    sh[t] = (i < NN) ? g_cnt[i] : 0;
    __syncthreads();
    for (int off = 512; off; off >>= 1) {
        if (t < off) sh[t] += sh[t + off];
        __syncthreads();
    }
    if (t == 0) g_bsum[b] = sh[0];
}

__global__ void k_bscan(int etot) {
    __shared__ int s[NB];
    int t = threadIdx.x;
    if (t < NB) s[t] = g_bsum[t];
    __syncthreads();
    if (t == 0) {
        int run = 0;
        for (int b = 0; b < NB; b++) { int v = s[b]; s[b] = run; run += v; }
    }
    __syncthreads();
    if (t < NB) g_boff[t] = s[t];
    if (t == 0) g_rp[NN] = etot;
}

__global__ void k_rp() {
    __shared__ int sh[1024];
    int b = blockIdx.x, t = threadIdx.x, i = b * 1024 + t;
    int v = (i < NN) ? g_cnt[i] : 0;
    sh[t] = v;
    __syncthreads();
    for (int off = 1; off < 1024; off <<= 1) {
        int cur = sh[t];
        int u = (t >= off) ? sh[t - off] : 0;
        __syncthreads();
        sh[t] = cur + u;
        __syncthreads();
    }
    if (i < NN) {
        int rp = g_boff[b] + sh[t] - v;    // exclusive
        g_rp[i]   = rp;
        g_fill[i] = rp + 1;                // slot 0 = self loop
        g_csr[rp] = i;
    }
}

// 4 edges per thread, int4 loads.
__global__ void k_scatter(const int* __restrict__ ei, int E) {
    int i0 = (blockIdx.x * blockDim.x + threadIdx.x) * 4;
    if (i0 >= E) return;
    int4 s4 = *(const int4*)(ei + i0);
    int4 d4 = *(const int4*)(ei + E + i0);
    int p0 = atomicAdd(&g_fill[d4.x], 1);
    int p1 = atomicAdd(&g_fill[d4.y], 1);
    int p2 = atomicAdd(&g_fill[d4.z], 1);
    int p3 = atomicAdd(&g_fill[d4.w], 1);
    g_csr[p0] = s4.x;
    g_csr[p1] = s4.y;
    g_csr[p2] = s4.z;
    g_csr[p3] = s4.w;
}

// ---------------- GEMM1 + attention projections, register-tiled --------------
// 64 nodes per tile; thread = 4 rows x 4 cols micro-tile. Persistent.
#define GEMM_BLOCKS 1184
#define NTILES      ((NN + 63) / 64)       // 1563 (last tile partial)
__global__ void k_gemm1(const float* __restrict__ x, const float* __restrict__ W,
                        const float* __restrict__ as, const float* __restrict__ ad) {
    __shared__ float4 sW4[64 * 16];    // sW4[k*16+ci] = W[k][4ci..4ci+3]
    __shared__ float  sx[64 * 64];     // 64 node rows
    __shared__ float  ss[64], sd[64];
    int t = threadIdx.x;
    for (int i = t; i < 1024; i += 256) sW4[i] = ((const float4*)W)[i];
    if (t < 64) { ss[t] = as[t]; sd[t] = ad[t]; }
    int ci = t & 15, rgl = t >> 4;     // col-group 0..15, row-group 0..15 (4 rows)

    for (int tile = blockIdx.x; tile < NTILES; tile += GEMM_BLOCKS) {
        __syncthreads();
        {   // load 64 rows (1024 float4), guarded for the last partial tile
            const float4* xg = (const float4*)x;
            int base4 = tile * 1024;
#pragma unroll
            for (int r = 0; r < 4; r++) {
                int idx = t + r * 256;
                int g = base4 + idx;
                ((float4*)sx)[idx] = (g < NN * 16) ? xg[g]
                                   : make_float4(0.f, 0.f, 0.f, 0.f);
            }
        }
        __syncthreads();

        const float* x0 = &sx[(rgl * 4 + 0) * 64];
        const float* x1 = &sx[(rgl * 4 + 1) * 64];
        const float* x2 = &sx[(rgl * 4 + 2) * 64];
        const float* x3 = &sx[(rgl * 4 + 3) * 64];
        float a0[4] = {0.f, 0.f, 0.f, 0.f};
        float a1[4] = {0.f, 0.f, 0.f, 0.f};
        float a2[4] = {0.f, 0.f, 0.f, 0.f};
        float a3[4] = {0.f, 0.f, 0.f, 0.f};
#pragma unroll
        for (int k = 0; k < 64; k += 4) {
            float4 xa = *(const float4*)(x0 + k);
            float4 xb = *(const float4*)(x1 + k);
            float4 xc = *(const float4*)(x2 + k);
            float4 xd = *(const float4*)(x3 + k);
#pragma unroll
            for (int kk = 0; kk < 4; kk++) {
                float4 wv = sW4[(k + kk) * 16 + ci];
                float va = (&xa.x)[kk], vb = (&xb.x)[kk];
                float vc = (&xc.x)[kk], vd = (&xd.x)[kk];
                a0[0] = fmaf(va, wv.x, a0[0]); a0[1] = fmaf(va, wv.y, a0[1]);
                a0[2] = fmaf(va, wv.z, a0[2]); a0[3] = fmaf(va, wv.w, a0[3]);
                a1[0] = fmaf(vb, wv.x, a1[0]); a1[1] = fmaf(vb, wv.y, a1[1]);
                a1[2] = fmaf(vb, wv.z, a1[2]); a1[3] = fmaf(vb, wv.w, a1[3]);
                a2[0] = fmaf(vc, wv.x, a2[0]); a2[1] = fmaf(vc, wv.y, a2[1]);
                a2[2] = fmaf(vc, wv.z, a2[2]); a2[3] = fmaf(vc, wv.w, a2[3]);
                a3[0] = fmaf(vd, wv.x, a3[0]); a3[1] = fmaf(vd, wv.y, a3[1]);
                a3[2] = fmaf(vd, wv.z, a3[2]); a3[3] = fmaf(vd, wv.w, a3[3]);
            }
        }
        int n0 = tile * 64 + rgl * 4;
        float* rows[4] = {a0, a1, a2, a3};
#pragma unroll
        for (int r = 0; r < 4; r++) {
            int n = n0 + r;
            if (n >= NN) break;
            float* a = rows[r];
            __half2 p0 = __floats2half2_rn(a[0], a[1]);
            __half2 p1 = __floats2half2_rn(a[2], a[3]);
            __half2* hp = (__half2*)(g_h1h + (size_t)n * 64 + 4 * ci);
            hp[0] = p0; hp[1] = p1;
            float sv = a[0] * ss[4 * ci] + a[1] * ss[4 * ci + 1]
                     + a[2] * ss[4 * ci + 2] + a[3] * ss[4 * ci + 3];
            float dv = a[0] * sd[4 * ci] + a[1] * sd[4 * ci + 1]
                     + a[2] * sd[4 * ci + 2] + a[3] * sd[4 * ci + 3];
#pragma unroll
            for (int off = 1; off <= 2; off <<= 1) {
                sv += __shfl_xor_sync(0xffffffffu, sv, off);
                dv += __shfl_xor_sync(0xffffffffu, dv, off);
            }
            if ((ci & 3) == 0) {
                int head = ci >> 2;
                ((float*)&g_as1[n])[head] = sv;
                ((float*)&g_ad1[n])[head] = dv;
            }
        }
    }
}

// ---------------- layer1 aggregation: warp per dst, fp16 gather ----------------
__global__ void k_agg1(const float* __restrict__ b1, const float* __restrict__ W2,
                       const float* __restrict__ as2p, const float* __restrict__ ad2p) {
    __shared__ int   ssrc[8][32];
    __shared__ float seT[8][4][33];            // [warp][head][edge], pad 33
    int lane = threadIdx.x & 31, w = threadIdx.x >> 5;
    int d = blockIdx.x * 8 + w;
    if (d >= NN) return;
    int base = g_rp[d];
    int deg  = g_rp[d + 1] - base;
    float4 ad = g_ad1[d];

    int hh = lane >> 3;                         // head of channels 2l,2l+1
    float acc0 = 0.f, acc1 = 0.f;
    float d0 = 0.f, d1 = 0.f, d2 = 0.f, d3 = 0.f;

    for (int chunk = 0; chunk < deg; chunk += 32) {
        int i = chunk + lane;
        int s = 0;
        float e0 = 0.f, e1 = 0.f, e2 = 0.f, e3 = 0.f;
        if (i < deg) {
            s = g_csr[base + i];
            float4 a = g_as1[s];
            e0 = __expf(lrelu(a.x + ad.x)); d0 += e0;
            e1 = __expf(lrelu(a.y + ad.y)); d1 += e1;
            e2 = __expf(lrelu(a.z + ad.z)); d2 += e2;
            e3 = __expf(lrelu(a.w + ad.w)); d3 += e3;
        }
        __syncwarp();
        ssrc[w][lane] = s;
        seT[w][0][lane] = e0; seT[w][1][lane] = e1;
        seT[w][2][lane] = e2; seT[w][3][lane] = e3;
        __syncwarp();
        int cnt = deg - chunk; if (cnt > 32) cnt = 32;
        int j = 0;
        for (; j + 8 <= cnt; j += 8) {
            __half2 v[8]; float ew[8];
#pragma unroll
            for (int k = 0; k < 8; k++) {
                int sj = ssrc[w][j + k];
                v[k]  = ((const __half2*)(g_h1h + (size_t)sj * 64))[lane];
                ew[k] = seT[w][hh][j + k];
            }
#pragma unroll
            for (int k = 0; k < 8; k++) {
                float2 f = __half22float2(v[k]);
                acc0 = fmaf(f.x, ew[k], acc0);
                acc1 = fmaf(f.y, ew[k], acc1);
            }
        }
        for (; j < cnt; j++) {
            int sj = ssrc[w][j];
            __half2 vv = ((const __half2*)(g_h1h + (size_t)sj * 64))[lane];
            float ew = seT[w][hh][j];
            float2 f = __half22float2(vv);
            acc0 = fmaf(f.x, ew, acc0);
            acc1 = fmaf(f.y, ew, acc1);
        }
    }
#pragma unroll
    for (int off = 16; off; off >>= 1) {
        d0 += __shfl_xor_sync(0xffffffffu, d0, off);
        d1 += __shfl_xor_sync(0xffffffffu, d1, off);
        d2 += __shfl_xor_sync(0xffffffffu, d2, off);
        d3 += __shfl_xor_sync(0xffffffffu, d3, off);
    }

    float den = (hh == 0 ? d0 : hh == 1 ? d1 : hh == 2 ? d2 : d3) + EPSV;
    float2 bb = ((const float2*)b1)[lane];
    float2 ww = ((const float2*)W2)[lane];
    float v0 = acc0 / den + bb.x;
    float v1 = acc1 / den + bb.y;
    v0 = v0 > 0.f ? v0 : (__expf(v0) - 1.f);
    v1 = v1 > 0.f ? v1 : (__expf(v1) - 1.f);
    float h2 = v0 * ww.x + v1 * ww.y;
#pragma unroll
    for (int off = 16; off; off >>= 1) h2 += __shfl_xor_sync(0xffffffffu, h2, off);
    if (lane == 0) {
        g_sh2[d] = make_float2(h2 * as2p[0], h2);
        g_ad2[d] = h2 * ad2p[0];
    }
}

// ---------------- layer2 aggregation + final output ---------------------------
__global__ void k_agg2(float* __restrict__ out, const float* __restrict__ b2) {
    int lane = threadIdx.x & 31, warp = threadIdx.x >> 5;
    int d = blockIdx.x * 8 + warp;
    if (d >= NN) return;
    int base = g_rp[d];
    int deg  = g_rp[d + 1] - base;
    float adv = g_ad2[d];

    float num = 0.f, den = 0.f;
    for (int i = lane; i < deg; i += 32) {
        int s = g_csr[base + i];
        float2 sh = g_sh2[s];
        float e = __expf(lrelu(sh.x + adv));
        num = fmaf(e, sh.y, num);
        den += e;
    }
#pragma unroll
    for (int off = 16; off; off >>= 1) {
        num += __shfl_xor_sync(0xffffffffu, num, off);
        den += __shfl_xor_sync(0xffffffffu, den, off);
    }
    if (lane == 0) out[d] = num / (den + EPSV) + b2[0];
}

// ---------------- launch -----------------------------------------------------
extern "C" void kernel_launch(void* const* d_in, const int* in_sizes, int n_in,
                              void* d_out, int out_size) {
    const float* x    = (const float*)d_in[0];
    const int*   ei   = (const int*)d_in[1];
    const float* W1   = (const float*)d_in[2];
    const float* as1  = (const float*)d_in[3];
    const float* ad1  = (const float*)d_in[4];
    const float* b1   = (const float*)d_in[5];
    const float* W2   = (const float*)d_in[6];
    const float* as2  = (const float*)d_in[7];
    const float* ad2  = (const float*)d_in[8];
    const float* b2   = (const float*)d_in[9];
    float*       out  = (float*)d_out;

    int E    = in_sizes[1] / 2;
    int etot = E + NN;
    int eb4  = (E / 4 + 255) / 256;

    k_zero   <<<(NN + 255) / 256, 256>>>();
    k_hist   <<<eb4, 256>>>(ei, E);
    k_bsum   <<<NB, 1024>>>();
    k_gemm1  <<<GEMM_BLOCKS, 256>>>(x, W1, as1, ad1);   // idx 3: ncu capture target
    k_bscan  <<<1, 128>>>(etot);
    k_rp     <<<NB, 1024>>>();
    k_scatter<<<eb4, 256>>>(ei, E);
    k_agg1   <<<NN / 8, 256>>>(b1, W2, as2, ad2);
    k_agg2   <<<NN / 8, 256>>>(out, b2);
}